// round 8
// baseline (speedup 1.0000x reference)
#include <cuda_runtime.h>
#include <cuda_bf16.h>
#include <float.h>

// ROI pooling: crop_and_resize (bilinear, 14x14) + 2x2 max pool -> (N,7,7,512)
// feature_map: (1, 50, 75, 512) fp32 NHWC ; rois: (N,4) [x1,y1,x2,y2] ; img_size: (2,) int32
//
// grid = (N, 7 pooled rows), block = 256 threads, each thread owns ONE float2
// (2 channels) -> halved per-thread register state vs float4 so more CTAs/SM
// keep the L1 queue full. Block-uniform shared-middle-row condition hoisted
// into two specialized branch-free paths. Validity mask folded into weights.

#define FH 50
#define FW 75
#define FC 512
#define NPOOL 7
#define CROPDIM 14
#define C2 (FC / 2)            // 256 float2 chunks
#define ROWSTRIDE (FW * C2)    // float2 units per feature row

__device__ __forceinline__ float2 lerp2(const float2 a, const float2 b,
                                        const float wa, const float wb) {
    float2 h;
    h.x = fmaf(b.x, wb, a.x * wa);
    h.y = fmaf(b.y, wb, a.y * wa);
    return h;
}

__device__ __forceinline__ float2 max2(const float2 a, const float2 b) {
    float2 m;
    m.x = fmaxf(a.x, b.x);
    m.y = fmaxf(a.y, b.y);
    return m;
}

struct XCol {
    int   cA, cB;
    float wxg, omwxg;
};

__device__ __forceinline__ XCol xcol(const int k, const float sx, const float xb,
                                     const float fw) {
    XCol c;
    const float xs = fmaf((float)k, sx, xb);
    const float gx = ((xs >= 0.0f) && (xs <= fw)) ? 1.0f : 0.0f;
    const float x0 = floorf(xs);
    const float wx = xs - x0;
    int xi = min(max((int)x0, 0), FW - 1);
    c.cA = xi * C2;
    c.cB = min(xi + 1, FW - 1) * C2;
    c.wxg   = wx * gx;
    c.omwxg = (1.0f - wx) * gx;
    return c;
}

__global__ __launch_bounds__(256) void roi_pool_kernel(
    const float* __restrict__ fmap,
    const float* __restrict__ rois,
    const int*   __restrict__ img_size,
    float*       __restrict__ out)
{
    const int n  = blockIdx.x;   // roi index
    const int py = blockIdx.y;   // pooled row 0..6
    const int c2 = threadIdx.x;  // float2 channel chunk 0..255

    // ---- uniform per-block scalar setup ----
    const float ih = (float)img_size[0] - 1.0f;   // 799
    const float iw = (float)img_size[1] - 1.0f;   // 1199
    const float4 r = reinterpret_cast<const float4*>(rois)[n]; // x1,y1,x2,y2
    const float bx1 = r.x / iw;
    const float by1 = r.y / ih;
    const float bx2 = r.z / iw;
    const float by2 = r.w / ih;

    const float fh = (float)(FH - 1);   // 49
    const float fw = (float)(FW - 1);   // 74
    const float sy = (by2 - by1) * fh * (1.0f / (CROPDIM - 1));
    const float sx = (bx2 - bx1) * fw * (1.0f / (CROPDIM - 1));
    const float yb = by1 * fh;
    const float xb = bx1 * fw;

    // two crop rows feeding this pooled row (uniform scalars)
    int   row0, row1, row2, row3;
    float wyg0, omwyg0, wyg1, omwyg1;
    {
        const float ys0 = fmaf((float)(2 * py), sy, yb);
        const float gy0 = ((ys0 >= 0.0f) && (ys0 <= fh)) ? 1.0f : 0.0f;
        const float fl0 = floorf(ys0);
        const float wy0 = ys0 - fl0;
        int yi0 = min(max((int)fl0, 0), FH - 1);
        row0 = yi0 * ROWSTRIDE;
        row1 = min(yi0 + 1, FH - 1) * ROWSTRIDE;
        wyg0 = wy0 * gy0;  omwyg0 = (1.0f - wy0) * gy0;

        const float ys1 = fmaf((float)(2 * py + 1), sy, yb);
        const float gy1 = ((ys1 >= 0.0f) && (ys1 <= fh)) ? 1.0f : 0.0f;
        const float fl1 = floorf(ys1);
        const float wy1 = ys1 - fl1;
        int yi1 = min(max((int)fl1, 0), FH - 1);
        row2 = yi1 * ROWSTRIDE;
        row3 = min(yi1 + 1, FH - 1) * ROWSTRIDE;
        wyg1 = wy1 * gy1;  omwyg1 = (1.0f - wy1) * gy1;
    }

    const float2* __restrict__ fb = reinterpret_cast<const float2*>(fmap) + c2;
    float2* __restrict__ ob = reinterpret_cast<float2*>(out)
        + ((long)n * (NPOOL * NPOOL) + py * NPOOL) * C2 + c2;

    if (row2 == row1) {
        // ---- shared middle feature row: 3 distinct rows, 6 loads per sample ----
#pragma unroll
        for (int px = 0; px < NPOOL; px++) {
            float2 v[2][2];
#pragma unroll
            for (int i = 0; i < 2; i++) {
                const XCol c = xcol(2 * px + i, sx, xb, fw);
                const float2 a0 = __ldg(fb + row0 + c.cA);
                const float2 b0 = __ldg(fb + row0 + c.cB);
                const float2 a1 = __ldg(fb + row1 + c.cA);
                const float2 b1 = __ldg(fb + row1 + c.cB);
                const float2 a3 = __ldg(fb + row3 + c.cA);
                const float2 b3 = __ldg(fb + row3 + c.cB);
                const float2 h0 = lerp2(a0, b0, c.omwxg, c.wxg);
                const float2 h1 = lerp2(a1, b1, c.omwxg, c.wxg);
                const float2 h3 = lerp2(a3, b3, c.omwxg, c.wxg);
                v[i][0] = lerp2(h0, h1, omwyg0, wyg0);
                v[i][1] = lerp2(h1, h3, omwyg1, wyg1);
            }
            ob[px * C2] = max2(max2(v[0][0], v[0][1]), max2(v[1][0], v[1][1]));
        }
    } else {
        // ---- generic: 4 distinct rows, 8 loads per sample ----
#pragma unroll
        for (int px = 0; px < NPOOL; px++) {
            float2 v[2][2];
#pragma unroll
            for (int i = 0; i < 2; i++) {
                const XCol c = xcol(2 * px + i, sx, xb, fw);
                const float2 a0 = __ldg(fb + row0 + c.cA);
                const float2 b0 = __ldg(fb + row0 + c.cB);
                const float2 a1 = __ldg(fb + row1 + c.cA);
                const float2 b1 = __ldg(fb + row1 + c.cB);
                const float2 a2 = __ldg(fb + row2 + c.cA);
                const float2 b2 = __ldg(fb + row2 + c.cB);
                const float2 a3 = __ldg(fb + row3 + c.cA);
                const float2 b3 = __ldg(fb + row3 + c.cB);
                const float2 h0 = lerp2(a0, b0, c.omwxg, c.wxg);
                const float2 h1 = lerp2(a1, b1, c.omwxg, c.wxg);
                const float2 h2 = lerp2(a2, b2, c.omwxg, c.wxg);
                const float2 h3 = lerp2(a3, b3, c.omwxg, c.wxg);
                v[i][0] = lerp2(h0, h1, omwyg0, wyg0);
                v[i][1] = lerp2(h2, h3, omwyg1, wyg1);
            }
            ob[px * C2] = max2(max2(v[0][0], v[0][1]), max2(v[1][0], v[1][1]));
        }
    }
}

extern "C" void kernel_launch(void* const* d_in, const int* in_sizes, int n_in,
                              void* d_out, int out_size) {
    const float* fmap     = (const float*)d_in[0];
    const float* rois     = (const float*)d_in[1];
    const int*   img_size = (const int*)d_in[2];
    float* out = (float*)d_out;

    const int N = in_sizes[1] / 4;   // number of rois
    dim3 grid(N, NPOOL);
    roi_pool_kernel<<<grid, 256>>>(fmap, rois, img_size, out);
}

// round 9
// speedup vs baseline: 1.1431x; 1.1431x over previous
#include <cuda_runtime.h>
#include <cuda_bf16.h>
#include <float.h>

// ROI pooling: crop_and_resize (bilinear, 14x14) + 2x2 max pool -> (N,7,7,512)
// feature_map: (1, 50, 75, 512) fp32 NHWC ; rois: (N,4) [x1,y1,x2,y2] ; img_size: (2,) int32
//
// grid = (N, 7 pooled rows), block = 128 threads, one float4 (4 channels)/thread.
// __launch_bounds__(128,12) forces regs<=42 so 12 CTAs/SM keep the L1 queue full.
// Block-uniform shared-middle-row condition hoisted into two branch-free paths.
// Validity mask folded into scalar weights.

#define FH 50
#define FW 75
#define FC 512
#define NPOOL 7
#define CROPDIM 14
#define C4 (FC / 4)
#define ROWSTRIDE (FW * C4)

__device__ __forceinline__ float4 lerp4(const float4 a, const float4 b,
                                        const float wa, const float wb) {
    float4 h;
    h.x = fmaf(b.x, wb, a.x * wa);
    h.y = fmaf(b.y, wb, a.y * wa);
    h.z = fmaf(b.z, wb, a.z * wa);
    h.w = fmaf(b.w, wb, a.w * wa);
    return h;
}

__device__ __forceinline__ float4 max4(const float4 a, const float4 b) {
    float4 m;
    m.x = fmaxf(a.x, b.x);
    m.y = fmaxf(a.y, b.y);
    m.z = fmaxf(a.z, b.z);
    m.w = fmaxf(a.w, b.w);
    return m;
}

struct XCol {
    int   cA, cB;
    float wxg, omwxg;
};

__device__ __forceinline__ XCol xcol(const int k, const float sx, const float xb,
                                     const float fw) {
    XCol c;
    const float xs = fmaf((float)k, sx, xb);
    const float gx = ((xs >= 0.0f) && (xs <= fw)) ? 1.0f : 0.0f;
    const float x0 = floorf(xs);
    const float wx = xs - x0;
    int xi = min(max((int)x0, 0), FW - 1);
    c.cA = xi * C4;
    c.cB = min(xi + 1, FW - 1) * C4;
    c.wxg   = wx * gx;
    c.omwxg = (1.0f - wx) * gx;
    return c;
}

__global__ __launch_bounds__(128, 12) void roi_pool_kernel(
    const float* __restrict__ fmap,
    const float* __restrict__ rois,
    const int*   __restrict__ img_size,
    float*       __restrict__ out)
{
    const int n  = blockIdx.x;   // roi index
    const int py = blockIdx.y;   // pooled row 0..6
    const int c4 = threadIdx.x;  // float4 channel chunk 0..127

    // ---- uniform per-block scalar setup ----
    const float ih = (float)img_size[0] - 1.0f;   // 799
    const float iw = (float)img_size[1] - 1.0f;   // 1199
    const float4 r = reinterpret_cast<const float4*>(rois)[n]; // x1,y1,x2,y2
    const float bx1 = r.x / iw;
    const float by1 = r.y / ih;
    const float bx2 = r.z / iw;
    const float by2 = r.w / ih;

    const float fh = (float)(FH - 1);   // 49
    const float fw = (float)(FW - 1);   // 74
    const float sy = (by2 - by1) * fh * (1.0f / (CROPDIM - 1));
    const float sx = (bx2 - bx1) * fw * (1.0f / (CROPDIM - 1));
    const float yb = by1 * fh;
    const float xb = bx1 * fw;

    // two crop rows feeding this pooled row (uniform scalars)
    int   row0, row1, row2, row3;
    float wyg0, omwyg0, wyg1, omwyg1;
    {
        const float ys0 = fmaf((float)(2 * py), sy, yb);
        const float gy0 = ((ys0 >= 0.0f) && (ys0 <= fh)) ? 1.0f : 0.0f;
        const float fl0 = floorf(ys0);
        const float wy0 = ys0 - fl0;
        int yi0 = min(max((int)fl0, 0), FH - 1);
        row0 = yi0 * ROWSTRIDE;
        row1 = min(yi0 + 1, FH - 1) * ROWSTRIDE;
        wyg0 = wy0 * gy0;  omwyg0 = (1.0f - wy0) * gy0;

        const float ys1 = fmaf((float)(2 * py + 1), sy, yb);
        const float gy1 = ((ys1 >= 0.0f) && (ys1 <= fh)) ? 1.0f : 0.0f;
        const float fl1 = floorf(ys1);
        const float wy1 = ys1 - fl1;
        int yi1 = min(max((int)fl1, 0), FH - 1);
        row2 = yi1 * ROWSTRIDE;
        row3 = min(yi1 + 1, FH - 1) * ROWSTRIDE;
        wyg1 = wy1 * gy1;  omwyg1 = (1.0f - wy1) * gy1;
    }

    const float4* __restrict__ fb = reinterpret_cast<const float4*>(fmap) + c4;
    float4* __restrict__ ob = reinterpret_cast<float4*>(out)
        + ((long)n * (NPOOL * NPOOL) + py * NPOOL) * C4 + c4;

    if (row2 == row1) {
        // ---- shared middle feature row: 3 distinct rows, 6 loads per sample ----
#pragma unroll
        for (int px = 0; px < NPOOL; px++) {
            float4 v[2][2];
#pragma unroll
            for (int i = 0; i < 2; i++) {
                const XCol c = xcol(2 * px + i, sx, xb, fw);
                const float4 a0 = __ldg(fb + row0 + c.cA);
                const float4 b0 = __ldg(fb + row0 + c.cB);
                const float4 a1 = __ldg(fb + row1 + c.cA);
                const float4 b1 = __ldg(fb + row1 + c.cB);
                const float4 a3 = __ldg(fb + row3 + c.cA);
                const float4 b3 = __ldg(fb + row3 + c.cB);
                const float4 h0 = lerp4(a0, b0, c.omwxg, c.wxg);
                const float4 h1 = lerp4(a1, b1, c.omwxg, c.wxg);
                const float4 h3 = lerp4(a3, b3, c.omwxg, c.wxg);
                v[i][0] = lerp4(h0, h1, omwyg0, wyg0);
                v[i][1] = lerp4(h1, h3, omwyg1, wyg1);
            }
            ob[px * C4] = max4(max4(v[0][0], v[0][1]), max4(v[1][0], v[1][1]));
        }
    } else {
        // ---- generic: 4 distinct rows, 8 loads per sample ----
#pragma unroll
        for (int px = 0; px < NPOOL; px++) {
            float4 v[2][2];
#pragma unroll
            for (int i = 0; i < 2; i++) {
                const XCol c = xcol(2 * px + i, sx, xb, fw);
                const float4 a0 = __ldg(fb + row0 + c.cA);
                const float4 b0 = __ldg(fb + row0 + c.cB);
                const float4 a1 = __ldg(fb + row1 + c.cA);
                const float4 b1 = __ldg(fb + row1 + c.cB);
                const float4 a2 = __ldg(fb + row2 + c.cA);
                const float4 b2 = __ldg(fb + row2 + c.cB);
                const float4 a3 = __ldg(fb + row3 + c.cA);
                const float4 b3 = __ldg(fb + row3 + c.cB);
                const float4 h0 = lerp4(a0, b0, c.omwxg, c.wxg);
                const float4 h1 = lerp4(a1, b1, c.omwxg, c.wxg);
                const float4 h2 = lerp4(a2, b2, c.omwxg, c.wxg);
                const float4 h3 = lerp4(a3, b3, c.omwxg, c.wxg);
                v[i][0] = lerp4(h0, h1, omwyg0, wyg0);
                v[i][1] = lerp4(h2, h3, omwyg1, wyg1);
            }
            ob[px * C4] = max4(max4(v[0][0], v[0][1]), max4(v[1][0], v[1][1]));
        }
    }
}

extern "C" void kernel_launch(void* const* d_in, const int* in_sizes, int n_in,
                              void* d_out, int out_size) {
    const float* fmap     = (const float*)d_in[0];
    const float* rois     = (const float*)d_in[1];
    const int*   img_size = (const int*)d_in[2];
    float* out = (float*)d_out;

    const int N = in_sizes[1] / 4;   // number of rois
    dim3 grid(N, NPOOL);
    roi_pool_kernel<<<grid, 128>>>(fmap, rois, img_size, out);
}

// round 10
// speedup vs baseline: 1.2407x; 1.0854x over previous
#include <cuda_runtime.h>
#include <cuda_bf16.h>
#include <float.h>

// ROI pooling: crop_and_resize (bilinear, 14x14) + 2x2 max pool -> (N,7,7,512)
// feature_map: (1, 50, 75, 512) fp32 NHWC ; rois: (N,4) [x1,y1,x2,y2] ; img_size: (2,) int32
//
// grid = (N, 7 pooled rows), block = 128 threads, one float4 (4 channels)/thread.
// __launch_bounds__(128,8): 64-reg budget lets ptxas front-batch the next px
// iteration's loads (deep MLP) at ~8 CTAs/SM -- measured sweet spot (more CTAs
// thrash L1 and regress). Streaming stores (__stcs) keep the write-only output
// from evicting gather lines in L2. Block-uniform shared-middle-row condition
// hoisted into two branch-free paths; validity mask folded into weights.

#define FH 50
#define FW 75
#define FC 512
#define NPOOL 7
#define CROPDIM 14
#define C4 (FC / 4)
#define ROWSTRIDE (FW * C4)

__device__ __forceinline__ float4 lerp4(const float4 a, const float4 b,
                                        const float wa, const float wb) {
    float4 h;
    h.x = fmaf(b.x, wb, a.x * wa);
    h.y = fmaf(b.y, wb, a.y * wa);
    h.z = fmaf(b.z, wb, a.z * wa);
    h.w = fmaf(b.w, wb, a.w * wa);
    return h;
}

__device__ __forceinline__ float4 max4(const float4 a, const float4 b) {
    float4 m;
    m.x = fmaxf(a.x, b.x);
    m.y = fmaxf(a.y, b.y);
    m.z = fmaxf(a.z, b.z);
    m.w = fmaxf(a.w, b.w);
    return m;
}

struct XCol {
    int   cA, cB;
    float wxg, omwxg;
};

__device__ __forceinline__ XCol xcol(const int k, const float sx, const float xb,
                                     const float fw) {
    XCol c;
    const float xs = fmaf((float)k, sx, xb);
    const float gx = ((xs >= 0.0f) && (xs <= fw)) ? 1.0f : 0.0f;
    const float x0 = floorf(xs);
    const float wx = xs - x0;
    int xi = min(max((int)x0, 0), FW - 1);
    c.cA = xi * C4;
    c.cB = min(xi + 1, FW - 1) * C4;
    c.wxg   = wx * gx;
    c.omwxg = (1.0f - wx) * gx;
    return c;
}

__global__ __launch_bounds__(128, 8) void roi_pool_kernel(
    const float* __restrict__ fmap,
    const float* __restrict__ rois,
    const int*   __restrict__ img_size,
    float*       __restrict__ out)
{
    const int n  = blockIdx.x;   // roi index
    const int py = blockIdx.y;   // pooled row 0..6
    const int c4 = threadIdx.x;  // float4 channel chunk 0..127

    // ---- uniform per-block scalar setup ----
    const float ih = (float)img_size[0] - 1.0f;   // 799
    const float iw = (float)img_size[1] - 1.0f;   // 1199
    const float4 r = reinterpret_cast<const float4*>(rois)[n]; // x1,y1,x2,y2
    const float bx1 = r.x / iw;
    const float by1 = r.y / ih;
    const float bx2 = r.z / iw;
    const float by2 = r.w / ih;

    const float fh = (float)(FH - 1);   // 49
    const float fw = (float)(FW - 1);   // 74
    const float sy = (by2 - by1) * fh * (1.0f / (CROPDIM - 1));
    const float sx = (bx2 - bx1) * fw * (1.0f / (CROPDIM - 1));
    const float yb = by1 * fh;
    const float xb = bx1 * fw;

    // two crop rows feeding this pooled row (uniform scalars)
    int   row0, row1, row2, row3;
    float wyg0, omwyg0, wyg1, omwyg1;
    {
        const float ys0 = fmaf((float)(2 * py), sy, yb);
        const float gy0 = ((ys0 >= 0.0f) && (ys0 <= fh)) ? 1.0f : 0.0f;
        const float fl0 = floorf(ys0);
        const float wy0 = ys0 - fl0;
        int yi0 = min(max((int)fl0, 0), FH - 1);
        row0 = yi0 * ROWSTRIDE;
        row1 = min(yi0 + 1, FH - 1) * ROWSTRIDE;
        wyg0 = wy0 * gy0;  omwyg0 = (1.0f - wy0) * gy0;

        const float ys1 = fmaf((float)(2 * py + 1), sy, yb);
        const float gy1 = ((ys1 >= 0.0f) && (ys1 <= fh)) ? 1.0f : 0.0f;
        const float fl1 = floorf(ys1);
        const float wy1 = ys1 - fl1;
        int yi1 = min(max((int)fl1, 0), FH - 1);
        row2 = yi1 * ROWSTRIDE;
        row3 = min(yi1 + 1, FH - 1) * ROWSTRIDE;
        wyg1 = wy1 * gy1;  omwyg1 = (1.0f - wy1) * gy1;
    }

    const float4* __restrict__ fb = reinterpret_cast<const float4*>(fmap) + c4;
    float4* __restrict__ ob = reinterpret_cast<float4*>(out)
        + ((long)n * (NPOOL * NPOOL) + py * NPOOL) * C4 + c4;

    if (row2 == row1) {
        // ---- shared middle feature row: 3 distinct rows, 6 loads per sample ----
#pragma unroll
        for (int px = 0; px < NPOOL; px++) {
            float4 v[2][2];
#pragma unroll
            for (int i = 0; i < 2; i++) {
                const XCol c = xcol(2 * px + i, sx, xb, fw);
                const float4 a0 = __ldg(fb + row0 + c.cA);
                const float4 b0 = __ldg(fb + row0 + c.cB);
                const float4 a1 = __ldg(fb + row1 + c.cA);
                const float4 b1 = __ldg(fb + row1 + c.cB);
                const float4 a3 = __ldg(fb + row3 + c.cA);
                const float4 b3 = __ldg(fb + row3 + c.cB);
                const float4 h0 = lerp4(a0, b0, c.omwxg, c.wxg);
                const float4 h1 = lerp4(a1, b1, c.omwxg, c.wxg);
                const float4 h3 = lerp4(a3, b3, c.omwxg, c.wxg);
                v[i][0] = lerp4(h0, h1, omwyg0, wyg0);
                v[i][1] = lerp4(h1, h3, omwyg1, wyg1);
            }
            const float4 m = max4(max4(v[0][0], v[0][1]), max4(v[1][0], v[1][1]));
            __stcs(&ob[px * C4], m);
        }
    } else {
        // ---- generic: 4 distinct rows, 8 loads per sample ----
#pragma unroll
        for (int px = 0; px < NPOOL; px++) {
            float4 v[2][2];
#pragma unroll
            for (int i = 0; i < 2; i++) {
                const XCol c = xcol(2 * px + i, sx, xb, fw);
                const float4 a0 = __ldg(fb + row0 + c.cA);
                const float4 b0 = __ldg(fb + row0 + c.cB);
                const float4 a1 = __ldg(fb + row1 + c.cA);
                const float4 b1 = __ldg(fb + row1 + c.cB);
                const float4 a2 = __ldg(fb + row2 + c.cA);
                const float4 b2 = __ldg(fb + row2 + c.cB);
                const float4 a3 = __ldg(fb + row3 + c.cA);
                const float4 b3 = __ldg(fb + row3 + c.cB);
                const float4 h0 = lerp4(a0, b0, c.omwxg, c.wxg);
                const float4 h1 = lerp4(a1, b1, c.omwxg, c.wxg);
                const float4 h2 = lerp4(a2, b2, c.omwxg, c.wxg);
                const float4 h3 = lerp4(a3, b3, c.omwxg, c.wxg);
                v[i][0] = lerp4(h0, h1, omwyg0, wyg0);
                v[i][1] = lerp4(h2, h3, omwyg1, wyg1);
            }
            const float4 m = max4(max4(v[0][0], v[0][1]), max4(v[1][0], v[1][1]));
            __stcs(&ob[px * C4], m);
        }
    }
}

extern "C" void kernel_launch(void* const* d_in, const int* in_sizes, int n_in,
                              void* d_out, int out_size) {
    const float* fmap     = (const float*)d_in[0];
    const float* rois     = (const float*)d_in[1];
    const int*   img_size = (const int*)d_in[2];
    float* out = (float*)d_out;

    const int N = in_sizes[1] / 4;   // number of rois
    dim3 grid(N, NPOOL);
    roi_pool_kernel<<<grid, 128>>>(fmap, rois, img_size, out);
}